// round 14
// baseline (speedup 1.0000x reference)
#include <cuda_runtime.h>
#include <cstdint>

// Problem constants (fixed by the dataset)
#define NTOT 4096
#define FDIM 128
#define HDIM 128
#define NG0  512          // nodes in graph 0 (only block with adjacency)
#define E_TOT 131072

// Single fused grid (ONE wave): xhat | edge | TMA-fill | B-waiters
#define XB    128         // xhat blocks: 32 rows each
#define EB    64          // edge blocks: 2048 edges each
#define FILLB 128         // TMA fill blocks: 512 KB each via cp.async.bulk
#define BB    128         // B waiter blocks (1024 warps x 16 cells)
#define F0    16          // fill blocks covering out rows < 512 (first 8 MB)
#define BID_E0 (XB)
#define BID_F0 (XB + EB)
#define BID_B0 (XB + EB + FILLB)
#define GRID   (XB + EB + FILLB + BB)
#define LISTCAP 24576

// Scratch (__device__ globals; self-cleaning each replay -> deterministic)
__device__ float g_Xhat[NG0 * HDIM];
__device__ float g_partials[XB];
__device__ int   g_A[NG0 * NG0];      // histogram; zeroed by B as it reads
__device__ int   g_list[LISTCAP];     // distinct graph-0 cells (first-toucher)
__device__ int   g_nlist;             // reset by finalizer
__device__ int   g_count;             // reset by finalizer
__device__ int   g_done;              // reset by finalizer
__device__ int   g_done_x;            // reset by finalizer
__device__ int   g_done_e;            // reset by finalizer
__device__ int   g_done_f0;           // reset by finalizer

// Shared memory union: fill needs 32 KB zero buffer; xhat needs ~21.6 KB tiles.
#define SMEM_BYTES 33024

__device__ __forceinline__ uint32_t smem_u32(const void* p) {
    uint32_t a;
    asm("{ .reg .u64 t; cvta.to.shared.u64 t, %1; cvt.u32.u64 %0, t; }"
        : "=r"(a) : "l"(p));
    return a;
}

__global__ __launch_bounds__(256) void fusedK(const float* __restrict__ x,
                                              const float* __restrict__ W0,
                                              const float* __restrict__ b0,
                                              const int*   __restrict__ ei,
                                              const float* __restrict__ prob,
                                              float*       __restrict__ out) {
    __shared__ __align__(16) char smem_raw[SMEM_BYTES];

    int b   = blockIdx.x;
    int tid = threadIdx.x;

    // ======================== TMA FILL role =================================
    if (b >= BID_F0 && b < BID_B0) {
        int f = b - BID_F0;
        // zero the 32 KB smem staging buffer
        float4* zb = (float4*)smem_raw;             // 2048 float4
        float4  z  = make_float4(0.f, 0.f, 0.f, 0.f);
        #pragma unroll
        for (int i = 0; i < 8; i++) zb[i * 256 + tid] = z;
        __syncthreads();

        if (tid == 0) {
            asm volatile("fence.proxy.async.shared::cta;" ::: "memory");
            uint32_t src = smem_u32(smem_raw);
            char* dst0 = (char*)out + (size_t)f * 524288;   // 512 KB per block
            #pragma unroll
            for (int i = 0; i < 16; i++) {
                asm volatile(
                    "cp.async.bulk.global.shared::cta.bulk_group [%0], [%1], %2;"
                    :: "l"(dst0 + (size_t)i * 32768), "r"(src), "r"(32768)
                    : "memory");
            }
            asm volatile("cp.async.bulk.commit_group;" ::: "memory");
            asm volatile("cp.async.bulk.wait_group 0;" ::: "memory");
            if (f < F0) {                          // rows < 512 complete
                __threadfence();
                atomicAdd(&g_done_f0, 1);
            }
        }
        return;
    }

    // ======================== EDGE role =====================================
    if (b >= BID_E0 && b < BID_F0) {
        int base = (b - BID_E0) * 2048;
        #pragma unroll
        for (int k = 0; k < 8; k++) {
            int e = base + k * 256 + tid;
            int s = ei[e];
            int d = ei[E_TOT + e];
            if ((unsigned)s < NG0 && (unsigned)d < NG0) {
                int aidx = s * NG0 + d;
                int old = atomicAdd(&g_A[aidx], 1);
                if (old == 0) {
                    int slot = atomicAdd(&g_nlist, 1);
                    if (slot < LISTCAP) g_list[slot] = aidx;
                }
            }
        }
        __threadfence();
        __syncthreads();
        if (tid == 0) atomicAdd(&g_done_e, 1);
        return;
    }

    // ======================== XHAT role (validated r10/r11 math) ============
    if (b < XB) {
        float (*ws_t)[132] = (float (*)[132])(smem_raw);            // 16896 B
        float (*xs_t)[36]  = (float (*)[36])(smem_raw + 16896);     //  4608 B
        float* warpsum     = (float*)(smem_raw + 21504);            //    32 B

        int row0 = b * 32;
        int rg   = tid & 7;
        int cg   = tid >> 3;

        float acc[4][4];
        {
            float4 bb = *(const float4*)&b0[cg * 4];
            #pragma unroll
            for (int i = 0; i < 4; i++) {
                acc[i][0] = bb.x; acc[i][1] = bb.y; acc[i][2] = bb.z; acc[i][3] = bb.w;
            }
        }

        for (int kc = 0; kc < FDIM; kc += 32) {
            __syncthreads();
            #pragma unroll
            for (int it = 0; it < 4; it++) {
                int idx = it * 256 + tid;
                int h = idx >> 3, c4 = (idx & 7) * 4;
                float4 v = *(const float4*)&W0[h * FDIM + kc + c4];
                ws_t[c4 + 0][h] = v.x; ws_t[c4 + 1][h] = v.y;
                ws_t[c4 + 2][h] = v.z; ws_t[c4 + 3][h] = v.w;
            }
            {
                int r = tid >> 3, c4 = (tid & 7) * 4;
                float4 v = *(const float4*)&x[(row0 + r) * FDIM + kc + c4];
                xs_t[c4 + 0][r] = v.x; xs_t[c4 + 1][r] = v.y;
                xs_t[c4 + 2][r] = v.z; xs_t[c4 + 3][r] = v.w;
            }
            __syncthreads();
            #pragma unroll
            for (int kk = 0; kk < 32; kk++) {
                float4 av = *(const float4*)&xs_t[kk][rg * 4];
                float4 bv = *(const float4*)&ws_t[kk][cg * 4];
                acc[0][0] = fmaf(av.x, bv.x, acc[0][0]);
                acc[0][1] = fmaf(av.x, bv.y, acc[0][1]);
                acc[0][2] = fmaf(av.x, bv.z, acc[0][2]);
                acc[0][3] = fmaf(av.x, bv.w, acc[0][3]);
                acc[1][0] = fmaf(av.y, bv.x, acc[1][0]);
                acc[1][1] = fmaf(av.y, bv.y, acc[1][1]);
                acc[1][2] = fmaf(av.y, bv.z, acc[1][2]);
                acc[1][3] = fmaf(av.y, bv.w, acc[1][3]);
                acc[2][0] = fmaf(av.z, bv.x, acc[2][0]);
                acc[2][1] = fmaf(av.z, bv.y, acc[2][1]);
                acc[2][2] = fmaf(av.z, bv.z, acc[2][2]);
                acc[2][3] = fmaf(av.z, bv.w, acc[2][3]);
                acc[3][0] = fmaf(av.w, bv.x, acc[3][0]);
                acc[3][1] = fmaf(av.w, bv.y, acc[3][1]);
                acc[3][2] = fmaf(av.w, bv.z, acc[3][2]);
                acc[3][3] = fmaf(av.w, bv.w, acc[3][3]);
            }
        }

        float ss = 0.f;
        bool store = (row0 < NG0);
        #pragma unroll
        for (int i = 0; i < 4; i++) {
            int r = row0 + rg * 4 + i;
            #pragma unroll
            for (int j = 0; j < 4; j++) ss += acc[i][j] * acc[i][j];
            if (store) {
                float4 v = make_float4(acc[i][0], acc[i][1], acc[i][2], acc[i][3]);
                *(float4*)&g_Xhat[r * HDIM + cg * 4] = v;
            }
        }

        #pragma unroll
        for (int off = 16; off > 0; off >>= 1) ss += __shfl_down_sync(0xffffffffu, ss, off);
        if ((tid & 31) == 0) warpsum[tid >> 5] = ss;
        __syncthreads();
        if (tid == 0) {
            float s = 0.f;
            for (int w = 0; w < 8; w++) s += warpsum[w];
            g_partials[b] = s;
        }
        __threadfence();
        __syncthreads();
        if (tid == 0) atomicAdd(&g_done_x, 1);
        return;
    }

    // ======================== B role (waiters, last bids) ====================
    {
        float* s_fro  = (float*)(smem_raw);
        int*   wcount = (int*)(smem_raw + 16);

        int wid  = tid >> 5;
        int lane = tid & 31;

        if (tid == 0) {
            while (atomicAdd(&g_done_x, 0) < XB ||
                   atomicAdd(&g_done_e, 0) < EB ||
                   atomicAdd(&g_done_f0, 0) < F0)
                __nanosleep(64);
        }
        __syncthreads();
        __threadfence();   // acquire

        if (tid == 0) {
            float s = 0.f;
            #pragma unroll
            for (int i = 0; i < XB; i++) s += g_partials[i];
            *s_fro = s;
        }
        __syncthreads();

        float fro = *s_fro;
        float p   = prob[0];
        int   nl  = g_nlist; if (nl > LISTCAP) nl = LISTCAP;
        int   gw  = (b - BID_B0) * 8 + wid;        // [0, 1024)
        int   nz  = 0;

        #pragma unroll
        for (int batch = 0; batch < 4; batch++) {
            bool  valid[4];
            int   aidxs[4], cnts[4];
            float part[4];

            #pragma unroll
            for (int t = 0; t < 4; t++) {
                int idx  = gw + (batch * 4 + t) * 1024;   // covers [0, 16384)
                valid[t] = (idx < nl);
                aidxs[t] = valid[t] ? g_list[idx] : 0;
            }
            #pragma unroll
            for (int t = 0; t < 4; t++)
                cnts[t] = valid[t] ? g_A[aidxs[t]] : 0;

            float4 av[4], bv[4];
            #pragma unroll
            for (int t = 0; t < 4; t++) {
                int s = aidxs[t] >> 9;
                int d = aidxs[t] & (NG0 - 1);
                av[t] = ((const float4*)&g_Xhat[s * HDIM])[lane];
                bv[t] = ((const float4*)&g_Xhat[d * HDIM])[lane];
            }
            #pragma unroll
            for (int t = 0; t < 4; t++) {
                float a = av[t].x * bv[t].x;
                a = fmaf(av[t].y, bv[t].y, a);
                a = fmaf(av[t].z, bv[t].z, a);
                part[t] = fmaf(av[t].w, bv[t].w, a);
            }
            #pragma unroll
            for (int off = 16; off > 0; off >>= 1) {
                #pragma unroll
                for (int t = 0; t < 4; t++)
                    part[t] += __shfl_xor_sync(0xffffffffu, part[t], off);
            }
            if (lane == 0) {
                #pragma unroll
                for (int t = 0; t < 4; t++) {
                    if (valid[t]) {
                        int aidx = aidxs[t];
                        g_A[aidx] = 0;             // self-clean for next replay
                        int s = aidx >> 9;
                        int d = aidx & (NG0 - 1);
                        float v = part[t] / fro - p + 0.5f * (float)cnts[t];
                        v = fmaxf(v, 0.f);
                        out[(size_t)s * NTOT + d] = v;
                        nz += (v > 0.f) ? 1 : 0;
                    }
                }
            }
        }

        if (lane == 0) wcount[wid] = nz;
        __syncthreads();
        if (tid == 0) {
            int t = 0;
            for (int w = 0; w < 8; w++) t += wcount[w];
            if (t) atomicAdd(&g_count, t);
            __threadfence();
            int ticket = atomicAdd(&g_done, 1);
            if (ticket == BB - 1) {                // last B block: finalize
                int total_nz = *(volatile int*)&g_count;
                out[(size_t)NTOT * NTOT]     = (float)total_nz / (float)E_TOT;
                out[(size_t)NTOT * NTOT + 1] = p;
                g_count   = 0;
                g_done    = 0;
                g_nlist   = 0;
                g_done_x  = 0;
                g_done_e  = 0;
                g_done_f0 = 0;
                __threadfence();
            }
        }
    }
}

// ---------------------------------------------------------------------------
extern "C" void kernel_launch(void* const* d_in, const int* in_sizes, int n_in,
                              void* d_out, int out_size) {
    // Defensive input mapping by (distinct) element counts.
    const float* x    = nullptr;   // 524288
    const float* W0   = nullptr;   // 16384
    const float* b0   = nullptr;   // 128
    const float* prob = nullptr;   // 1
    const int*   ei   = nullptr;   // 262144
    for (int i = 0; i < n_in; i++) {
        switch (in_sizes[i]) {
            case NTOT * FDIM:  x    = (const float*)d_in[i]; break;
            case HDIM * FDIM:  W0   = (const float*)d_in[i]; break;
            case HDIM:         b0   = (const float*)d_in[i]; break;
            case 1:            prob = (const float*)d_in[i]; break;
            case 2 * E_TOT:    ei   = (const int*)d_in[i];   break;
            default: break; // batch (4096) unused: implied by i/512
        }
    }
    float* out = (float*)d_out;

    fusedK<<<GRID, 256>>>(x, W0, b0, ei, prob, out);
}

// round 15
// speedup vs baseline: 1.1055x; 1.1055x over previous
#include <cuda_runtime.h>
#include <cstdint>

// Problem constants (fixed by the dataset)
#define NTOT 4096
#define FDIM 128
#define HDIM 128
#define NG0  512          // nodes in graph 0 (only block with adjacency)
#define E_TOT 131072

// Single fused grid (ONE wave): edge | xhat | TMA-fill | B-waiters
#define EB    128         // edge blocks: 1024 edges each (gates B -> first)
#define XB    128         // xhat blocks: 32 rows each
#define FILLB 128         // TMA fill blocks: 512 KB each via cp.async.bulk
#define BB    128         // B waiter blocks (1024 warps x 16 cells)
#define F0    16          // fill blocks covering out rows < 512 (first 8 MB)
#define BID_X0 (EB)
#define BID_F0 (EB + XB)
#define BID_B0 (EB + XB + FILLB)
#define GRID   (EB + XB + FILLB + BB)
#define LISTCAP 24576

// Scratch (__device__ globals; self-cleaning each replay -> deterministic)
__device__ float g_Xhat[NG0 * HDIM];
__device__ float g_partials[XB];
__device__ int   g_A[NG0 * NG0];      // histogram; zeroed by B as it reads
__device__ int   g_list[LISTCAP];     // distinct graph-0 cells (first-toucher)
__device__ int   g_nlist;             // reset by finalizer
__device__ int   g_count;             // reset by finalizer
__device__ int   g_done;              // reset by finalizer
__device__ int   g_done_x;            // reset by finalizer
__device__ int   g_done_e;            // reset by finalizer
__device__ int   g_done_f0;           // reset by finalizer

// Shared memory union: fill needs 32 KB zero buffer; xhat needs ~21.6 KB tiles.
#define SMEM_BYTES 33024

__device__ __forceinline__ uint32_t smem_u32(const void* p) {
    uint32_t a;
    asm("{ .reg .u64 t; cvta.to.shared.u64 t, %1; cvt.u32.u64 %0, t; }"
        : "=r"(a) : "l"(p));
    return a;
}

__global__ __launch_bounds__(256) void fusedK(const float* __restrict__ x,
                                              const float* __restrict__ W0,
                                              const float* __restrict__ b0,
                                              const int*   __restrict__ ei,
                                              const float* __restrict__ prob,
                                              float*       __restrict__ out) {
    __shared__ __align__(16) char smem_raw[SMEM_BYTES];

    int b   = blockIdx.x;
    int tid = threadIdx.x;

    // ======================== EDGE role: [0, 128) ===========================
    if (b < EB) {
        int lane = tid & 31;
        int base = b * 1024;
        #pragma unroll
        for (int k = 0; k < 4; k++) {
            int e = base + k * 256 + tid;            // always < E_TOT
            int s = ei[e];
            int d = ei[E_TOT + e];
            bool ing  = ((unsigned)s < NG0) && ((unsigned)d < NG0);
            int  aidx = ing ? (s * NG0 + d) : 0;
            bool claimed = false;
            if (ing) {
                int old = atomicAdd(&g_A[aidx], 1);
                claimed = (old == 0);
            }
            // warp-aggregated worklist append (kills the hot g_nlist counter)
            unsigned m = __ballot_sync(0xffffffffu, claimed);
            if (m) {
                int leader = __ffs(m) - 1;
                int slotbase = 0;
                if (lane == leader) slotbase = atomicAdd(&g_nlist, __popc(m));
                slotbase = __shfl_sync(0xffffffffu, slotbase, leader);
                if (claimed) {
                    int off = __popc(m & ((1u << lane) - 1u));
                    int slot = slotbase + off;
                    if (slot < LISTCAP) g_list[slot] = aidx;
                }
            }
        }
        __threadfence();
        __syncthreads();
        if (tid == 0) atomicAdd(&g_done_e, 1);
        return;
    }

    // ======================== XHAT role (validated r10/r11 math) ============
    if (b < BID_F0) {
        float (*ws_t)[132] = (float (*)[132])(smem_raw);            // 16896 B
        float (*xs_t)[36]  = (float (*)[36])(smem_raw + 16896);     //  4608 B
        float* warpsum     = (float*)(smem_raw + 21504);            //    32 B

        int xb   = b - BID_X0;
        int row0 = xb * 32;
        int rg   = tid & 7;
        int cg   = tid >> 3;

        float acc[4][4];
        {
            float4 bb = *(const float4*)&b0[cg * 4];
            #pragma unroll
            for (int i = 0; i < 4; i++) {
                acc[i][0] = bb.x; acc[i][1] = bb.y; acc[i][2] = bb.z; acc[i][3] = bb.w;
            }
        }

        for (int kc = 0; kc < FDIM; kc += 32) {
            __syncthreads();
            #pragma unroll
            for (int it = 0; it < 4; it++) {
                int idx = it * 256 + tid;
                int h = idx >> 3, c4 = (idx & 7) * 4;
                float4 v = *(const float4*)&W0[h * FDIM + kc + c4];
                ws_t[c4 + 0][h] = v.x; ws_t[c4 + 1][h] = v.y;
                ws_t[c4 + 2][h] = v.z; ws_t[c4 + 3][h] = v.w;
            }
            {
                int r = tid >> 3, c4 = (tid & 7) * 4;
                float4 v = *(const float4*)&x[(row0 + r) * FDIM + kc + c4];
                xs_t[c4 + 0][r] = v.x; xs_t[c4 + 1][r] = v.y;
                xs_t[c4 + 2][r] = v.z; xs_t[c4 + 3][r] = v.w;
            }
            __syncthreads();
            #pragma unroll
            for (int kk = 0; kk < 32; kk++) {
                float4 av = *(const float4*)&xs_t[kk][rg * 4];
                float4 bv = *(const float4*)&ws_t[kk][cg * 4];
                acc[0][0] = fmaf(av.x, bv.x, acc[0][0]);
                acc[0][1] = fmaf(av.x, bv.y, acc[0][1]);
                acc[0][2] = fmaf(av.x, bv.z, acc[0][2]);
                acc[0][3] = fmaf(av.x, bv.w, acc[0][3]);
                acc[1][0] = fmaf(av.y, bv.x, acc[1][0]);
                acc[1][1] = fmaf(av.y, bv.y, acc[1][1]);
                acc[1][2] = fmaf(av.y, bv.z, acc[1][2]);
                acc[1][3] = fmaf(av.y, bv.w, acc[1][3]);
                acc[2][0] = fmaf(av.z, bv.x, acc[2][0]);
                acc[2][1] = fmaf(av.z, bv.y, acc[2][1]);
                acc[2][2] = fmaf(av.z, bv.z, acc[2][2]);
                acc[2][3] = fmaf(av.z, bv.w, acc[2][3]);
                acc[3][0] = fmaf(av.w, bv.x, acc[3][0]);
                acc[3][1] = fmaf(av.w, bv.y, acc[3][1]);
                acc[3][2] = fmaf(av.w, bv.z, acc[3][2]);
                acc[3][3] = fmaf(av.w, bv.w, acc[3][3]);
            }
        }

        float ss = 0.f;
        bool store = (row0 < NG0);
        #pragma unroll
        for (int i = 0; i < 4; i++) {
            int r = row0 + rg * 4 + i;
            #pragma unroll
            for (int j = 0; j < 4; j++) ss += acc[i][j] * acc[i][j];
            if (store) {
                float4 v = make_float4(acc[i][0], acc[i][1], acc[i][2], acc[i][3]);
                *(float4*)&g_Xhat[r * HDIM + cg * 4] = v;
            }
        }

        #pragma unroll
        for (int off = 16; off > 0; off >>= 1) ss += __shfl_down_sync(0xffffffffu, ss, off);
        if ((tid & 31) == 0) warpsum[tid >> 5] = ss;
        __syncthreads();
        if (tid == 0) {
            float s = 0.f;
            for (int w = 0; w < 8; w++) s += warpsum[w];
            g_partials[xb] = s;
        }
        __threadfence();
        __syncthreads();
        if (tid == 0) atomicAdd(&g_done_x, 1);
        return;
    }

    // ======================== TMA FILL role =================================
    if (b < BID_B0) {
        int f = b - BID_F0;
        float4* zb = (float4*)smem_raw;             // 2048 float4 = 32 KB
        float4  z  = make_float4(0.f, 0.f, 0.f, 0.f);
        #pragma unroll
        for (int i = 0; i < 8; i++) zb[i * 256 + tid] = z;
        __syncthreads();

        if (tid == 0) {
            asm volatile("fence.proxy.async.shared::cta;" ::: "memory");
            uint32_t src = smem_u32(smem_raw);
            char* dst0 = (char*)out + (size_t)f * 524288;   // 512 KB per block
            #pragma unroll
            for (int i = 0; i < 16; i++) {
                asm volatile(
                    "cp.async.bulk.global.shared::cta.bulk_group [%0], [%1], %2;"
                    :: "l"(dst0 + (size_t)i * 32768), "r"(src), "r"(32768)
                    : "memory");
            }
            asm volatile("cp.async.bulk.commit_group;" ::: "memory");
            asm volatile("cp.async.bulk.wait_group 0;" ::: "memory");
            if (f < F0) {                          // rows < 512 complete
                __threadfence();
                atomicAdd(&g_done_f0, 1);
            }
        }
        return;
    }

    // ======================== B role (waiters, last bids) ====================
    {
        float* s_fro  = (float*)(smem_raw);
        int*   wcount = (int*)(smem_raw + 16);
        float* redbuf = (float*)(smem_raw + 64);   // 8 floats

        int wid  = tid >> 5;
        int lane = tid & 31;

        if (tid == 0) {
            while (atomicAdd(&g_done_x, 0) < XB ||
                   atomicAdd(&g_done_e, 0) < EB ||
                   atomicAdd(&g_done_f0, 0) < F0)
                __nanosleep(64);
        }
        __syncthreads();
        __threadfence();   // acquire

        // Parallel fro reduction: 128 lanes load one partial each
        {
            float v = (tid < XB) ? g_partials[tid] : 0.f;
            #pragma unroll
            for (int off = 16; off > 0; off >>= 1)
                v += __shfl_down_sync(0xffffffffu, v, off);
            if (lane == 0) redbuf[wid] = v;
            __syncthreads();
            if (tid == 0) {
                float s = 0.f;
                #pragma unroll
                for (int w = 0; w < 8; w++) s += redbuf[w];
                *s_fro = s;
            }
            __syncthreads();
        }

        float fro = *s_fro;
        float p   = prob[0];
        int   nl  = g_nlist; if (nl > LISTCAP) nl = LISTCAP;
        int   gw  = (b - BID_B0) * 8 + wid;        // [0, 1024)
        int   nz  = 0;

        #pragma unroll
        for (int batch = 0; batch < 4; batch++) {
            bool  valid[4];
            int   aidxs[4], cnts[4];
            float part[4];

            #pragma unroll
            for (int t = 0; t < 4; t++) {
                int idx  = gw + (batch * 4 + t) * 1024;   // covers [0, 16384)
                valid[t] = (idx < nl);
                aidxs[t] = valid[t] ? g_list[idx] : 0;
            }
            #pragma unroll
            for (int t = 0; t < 4; t++)
                cnts[t] = valid[t] ? g_A[aidxs[t]] : 0;

            float4 av[4], bv[4];
            #pragma unroll
            for (int t = 0; t < 4; t++) {
                int s = aidxs[t] >> 9;
                int d = aidxs[t] & (NG0 - 1);
                av[t] = ((const float4*)&g_Xhat[s * HDIM])[lane];
                bv[t] = ((const float4*)&g_Xhat[d * HDIM])[lane];
            }
            #pragma unroll
            for (int t = 0; t < 4; t++) {
                float a = av[t].x * bv[t].x;
                a = fmaf(av[t].y, bv[t].y, a);
                a = fmaf(av[t].z, bv[t].z, a);
                part[t] = fmaf(av[t].w, bv[t].w, a);
            }
            #pragma unroll
            for (int off = 16; off > 0; off >>= 1) {
                #pragma unroll
                for (int t = 0; t < 4; t++)
                    part[t] += __shfl_xor_sync(0xffffffffu, part[t], off);
            }
            if (lane == 0) {
                #pragma unroll
                for (int t = 0; t < 4; t++) {
                    if (valid[t]) {
                        int aidx = aidxs[t];
                        g_A[aidx] = 0;             // self-clean for next replay
                        int s = aidx >> 9;
                        int d = aidx & (NG0 - 1);
                        float v = part[t] / fro - p + 0.5f * (float)cnts[t];
                        v = fmaxf(v, 0.f);
                        out[(size_t)s * NTOT + d] = v;
                        nz += (v > 0.f) ? 1 : 0;
                    }
                }
            }
        }

        if (lane == 0) wcount[wid] = nz;
        __syncthreads();
        if (tid == 0) {
            int t = 0;
            for (int w = 0; w < 8; w++) t += wcount[w];
            if (t) atomicAdd(&g_count, t);
            __threadfence();
            int ticket = atomicAdd(&g_done, 1);
            if (ticket == BB - 1) {                // last B block: finalize
                int total_nz = *(volatile int*)&g_count;
                out[(size_t)NTOT * NTOT]     = (float)total_nz / (float)E_TOT;
                out[(size_t)NTOT * NTOT + 1] = p;
                g_count   = 0;
                g_done    = 0;
                g_nlist   = 0;
                g_done_x  = 0;
                g_done_e  = 0;
                g_done_f0 = 0;
                __threadfence();
            }
        }
    }
}

// ---------------------------------------------------------------------------
extern "C" void kernel_launch(void* const* d_in, const int* in_sizes, int n_in,
                              void* d_out, int out_size) {
    // Defensive input mapping by (distinct) element counts.
    const float* x    = nullptr;   // 524288
    const float* W0   = nullptr;   // 16384
    const float* b0   = nullptr;   // 128
    const float* prob = nullptr;   // 1
    const int*   ei   = nullptr;   // 262144
    for (int i = 0; i < n_in; i++) {
        switch (in_sizes[i]) {
            case NTOT * FDIM:  x    = (const float*)d_in[i]; break;
            case HDIM * FDIM:  W0   = (const float*)d_in[i]; break;
            case HDIM:         b0   = (const float*)d_in[i]; break;
            case 1:            prob = (const float*)d_in[i]; break;
            case 2 * E_TOT:    ei   = (const int*)d_in[i];   break;
            default: break; // batch (4096) unused: implied by i/512
        }
    }
    float* out = (float*)d_out;

    fusedK<<<GRID, 256>>>(x, W0, b0, ei, prob, out);
}